// round 15
// baseline (speedup 1.0000x reference)
#include <cuda_runtime.h>
#include <cstdint>
#include <math.h>

#define N_NODES 100000
#define N_EDGES 3200000
#define D_FEAT  512
#define HID     16

// gemm1 tiling — measured-best R10 config (do not touch)
#define TPB_G     64
#define TILE_ROWS 256
#define RPT       4
#define XPITCH    36
#define GSMEM_FLOATS (D_FEAT * HID + TILE_ROWS * XPITCH)   // 8192 + 9216
#define GSMEM_BYTES  (GSMEM_FLOATS * 4)                    // 69632 B

// ---------------- scratch (device globals; no allocation allowed) ----------
__device__ float g_t1[N_NODES * HID];
__device__ float g_h1[N_NODES * HID];
__device__ float g_t2[N_NODES * HID];
__device__ int   g_is64;

// ---------------- helpers --------------------------------------------------
__device__ __forceinline__ unsigned long long ffma2(unsigned long long a,
                                                    unsigned long long b,
                                                    unsigned long long c) {
    unsigned long long d;
    asm("fma.rn.f32x2 %0, %1, %2, %3;" : "=l"(d) : "l"(a), "l"(b), "l"(c));
    return d;
}

// ---------------- edge_index dtype detection (parallel) --------------------
__global__ void detect_kernel(const void* eiv) {
    __shared__ int any32;
    if (threadIdx.x == 0) any32 = 0;
    __syncthreads();
    const int* p = (const int*)eiv;
    int local = 0;
    for (int i = threadIdx.x; i < 2048; i += 256)
        if (p[2 * i + 1] != 0) local = 1;
    if (local) atomicOr(&any32, 1);
    __syncthreads();
    if (threadIdx.x == 0) g_is64 = !any32;
}

// ---------------- GEMM1: t1 = x @ W1 ; epilogue zeroes g_h1 and out --------
__global__ void __launch_bounds__(TPB_G) gemm1_kernel(
        const float* __restrict__ x, const float* __restrict__ W1,
        float* __restrict__ out) {
    extern __shared__ float sm[];
    float* Ws = sm;                       // 8192 floats (full W1)
    float* xs = sm + D_FEAT * HID;        // 256 x 36 floats

    const int t = threadIdx.x;

    for (int i = t; i < D_FEAT * HID / 4; i += TPB_G)
        ((float4*)Ws)[i] = ((const float4*)W1)[i];

    const int row0 = blockIdx.x * TILE_ROWS;

    unsigned long long acc[RPT][8];
#pragma unroll
    for (int r = 0; r < RPT; r++)
#pragma unroll
        for (int j = 0; j < 8; j++) acc[r][j] = 0ULL;

    for (int kt = 0; kt < D_FEAT / 32; kt++) {
        const int k0 = kt * 32;
        __syncthreads();
#pragma unroll
        for (int i = 0; i < 32; i++) {
            int v   = i * TPB_G + t;
            int lr  = v >> 3;
            int sub = v & 7;
            int gr  = row0 + lr;
            if (gr >= N_NODES) gr = N_NODES - 1;
            float4 val = *(const float4*)(x + (size_t)gr * D_FEAT + k0 + sub * 4);
            *(float4*)(xs + lr * XPITCH + sub * 4) = val;
        }
        __syncthreads();

#pragma unroll
        for (int kk4 = 0; kk4 < 8; kk4++) {
            float4 xv[RPT];
#pragma unroll
            for (int r = 0; r < RPT; r++)
                xv[r] = *(const float4*)(xs + (t + TPB_G * r) * XPITCH + kk4 * 4);
#pragma unroll
            for (int kk = 0; kk < 4; kk++) {
                const ulonglong2* wrow =
                    (const ulonglong2*)(Ws + (k0 + kk4 * 4 + kk) * HID);
                ulonglong2 w0 = wrow[0], w1 = wrow[1];
                ulonglong2 w2 = wrow[2], w3 = wrow[3];
#pragma unroll
                for (int r = 0; r < RPT; r++) {
                    float xe = ((const float*)&xv[r])[kk];
                    unsigned long long xp;
                    unsigned int xb = __float_as_uint(xe);
                    asm("mov.b64 %0, {%1, %1};" : "=l"(xp) : "r"(xb));
                    acc[r][0] = ffma2(xp, w0.x, acc[r][0]);
                    acc[r][1] = ffma2(xp, w0.y, acc[r][1]);
                    acc[r][2] = ffma2(xp, w1.x, acc[r][2]);
                    acc[r][3] = ffma2(xp, w1.y, acc[r][3]);
                    acc[r][4] = ffma2(xp, w2.x, acc[r][4]);
                    acc[r][5] = ffma2(xp, w2.y, acc[r][5]);
                    acc[r][6] = ffma2(xp, w3.x, acc[r][6]);
                    acc[r][7] = ffma2(xp, w3.y, acc[r][7]);
                }
            }
        }
    }

    const float4 z4 = make_float4(0.f, 0.f, 0.f, 0.f);
#pragma unroll
    for (int r = 0; r < RPT; r++) {
        int gr = row0 + t + TPB_G * r;
        if (gr < N_NODES) {
            float o[16];
#pragma unroll
            for (int j = 0; j < 8; j++) {
                unsigned int lo, hi;
                asm("mov.b64 {%0, %1}, %2;" : "=r"(lo), "=r"(hi) : "l"(acc[r][j]));
                o[2 * j]     = __uint_as_float(lo);
                o[2 * j + 1] = __uint_as_float(hi);
            }
            float4* dst = (float4*)(g_t1 + (size_t)gr * HID);
            dst[0] = make_float4(o[0], o[1], o[2], o[3]);
            dst[1] = make_float4(o[4], o[5], o[6], o[7]);
            dst[2] = make_float4(o[8], o[9], o[10], o[11]);
            dst[3] = make_float4(o[12], o[13], o[14], o[15]);
            // fused zeroing of both accumulators for this row
            float4* h1 = (float4*)(g_h1 + (size_t)gr * HID);
            float4* ot = (float4*)(out  + (size_t)gr * HID);
            h1[0] = z4; h1[1] = z4; h1[2] = z4; h1[3] = z4;
            ot[0] = z4; ot[1] = z4; ot[2] = z4; ot[3] = z4;
        }
    }
}

// ---------------- edge scatter: acc[dst] += w * feat[src] ------------------
// One thread per (edge, 4-col chunk): proven best config (R1/R6/R12).
__global__ void scatter_kernel(const void* __restrict__ eiv,
                               const float* __restrict__ ew,
                               float* __restrict__ out, int pass) {
    long long u = (long long)blockIdx.x * blockDim.x + threadIdx.x;
    const long long total = (long long)N_EDGES * 4;
    if (u >= total) return;
    int e = (int)(u >> 2);
    int c = (int)(u & 3);

    const float* feat = (pass == 0) ? g_t1 : g_t2;
    float*       acc  = (pass == 0) ? g_h1 : out;

    long long s, d;
    if (!g_is64) {
        const int* ei = (const int*)eiv;
        s = ei[e];
        d = ei[N_EDGES + e];
    } else {
        const long long* ei = (const long long*)eiv;
        s = ei[e];
        d = ei[N_EDGES + e];
    }
    float w = ew[e];
    float4 v = *(const float4*)(feat + s * HID + c * 4);
    float4 m = make_float4(w * v.x, w * v.y, w * v.z, w * v.w);
    atomicAdd((float4*)(acc + d * HID + c * 4), m);
}

// ---------------- mid: t2 = relu(h1 + b1) @ W2 -----------------------------
__global__ void mid_kernel(const float* __restrict__ b1,
                           const float* __restrict__ W2) {
    __shared__ float W2s[HID * HID];
    __shared__ float b1s[HID];
    int t = threadIdx.x;
    if (t < HID * HID) W2s[t] = W2[t];
    if (t < HID) b1s[t] = b1[t];
    __syncthreads();

    int node = blockIdx.x * blockDim.x + t;
    if (node >= N_NODES) return;

    float v[16];
    const float4* src = (const float4*)(g_h1 + (size_t)node * HID);
#pragma unroll
    for (int q = 0; q < 4; q++) {
        float4 f = src[q];
        v[4 * q] = f.x; v[4 * q + 1] = f.y; v[4 * q + 2] = f.z; v[4 * q + 3] = f.w;
    }
#pragma unroll
    for (int i = 0; i < 16; i++) v[i] = fmaxf(v[i] + b1s[i], 0.0f);

    float o[16];
#pragma unroll
    for (int j = 0; j < 16; j++) o[j] = 0.0f;
#pragma unroll
    for (int i = 0; i < 16; i++) {
        float vi = v[i];
#pragma unroll
        for (int j = 0; j < 16; j++) o[j] = fmaf(vi, W2s[i * 16 + j], o[j]);
    }

    float4* dst = (float4*)(g_t2 + (size_t)node * HID);
    dst[0] = make_float4(o[0], o[1], o[2], o[3]);
    dst[1] = make_float4(o[4], o[5], o[6], o[7]);
    dst[2] = make_float4(o[8], o[9], o[10], o[11]);
    dst[3] = make_float4(o[12], o[13], o[14], o[15]);
}

// ---------------- final: out = log_softmax(out + b2) -----------------------
__global__ void final_kernel(float* __restrict__ out,
                             const float* __restrict__ b2) {
    __shared__ float b2s[HID];
    if (threadIdx.x < HID) b2s[threadIdx.x] = b2[threadIdx.x];
    __syncthreads();

    int node = blockIdx.x * blockDim.x + threadIdx.x;
    if (node >= N_NODES) return;

    float o[16];
    float4* p = (float4*)(out + (size_t)node * HID);
#pragma unroll
    for (int q = 0; q < 4; q++) {
        float4 f = p[q];
        o[4 * q]     = f.x + b2s[4 * q];
        o[4 * q + 1] = f.y + b2s[4 * q + 1];
        o[4 * q + 2] = f.z + b2s[4 * q + 2];
        o[4 * q + 3] = f.w + b2s[4 * q + 3];
    }
    float m = o[0];
#pragma unroll
    for (int j = 1; j < 16; j++) m = fmaxf(m, o[j]);
    float ssum = 0.0f;
#pragma unroll
    for (int j = 0; j < 16; j++) ssum += expf(o[j] - m);
    float lse = m + logf(ssum);
#pragma unroll
    for (int j = 0; j < 16; j++) o[j] -= lse;

    p[0] = make_float4(o[0], o[1], o[2], o[3]);
    p[1] = make_float4(o[4], o[5], o[6], o[7]);
    p[2] = make_float4(o[8], o[9], o[10], o[11]);
    p[3] = make_float4(o[12], o[13], o[14], o[15]);
}

// ---------------- launch ---------------------------------------------------
extern "C" void kernel_launch(void* const* d_in, const int* in_sizes, int n_in,
                              void* d_out, int out_size) {
    const float* x  = (const float*)d_in[0];
    const void*  ei = d_in[1];
    const float* ew = (const float*)d_in[2];
    const float* W1 = (const float*)d_in[3];
    const float* b1 = (const float*)d_in[4];
    const float* W2 = (const float*)d_in[5];
    const float* b2 = (const float*)d_in[6];
    float* out = (float*)d_out;

    static int smem_set = 0;
    if (!smem_set) {
        cudaFuncSetAttribute(gemm1_kernel,
                             cudaFuncAttributeMaxDynamicSharedMemorySize,
                             GSMEM_BYTES);
        smem_set = 1;
    }

    detect_kernel<<<1, 256>>>(ei);
    gemm1_kernel<<<(N_NODES + TILE_ROWS - 1) / TILE_ROWS, TPB_G,
                   GSMEM_BYTES>>>(x, W1, out);

    const int scat_blocks = (int)(((long long)N_EDGES * 4 + 255) / 256);
    scatter_kernel<<<scat_blocks, 256>>>(ei, ew, out, 0);
    mid_kernel<<<(N_NODES + 255) / 256, 256>>>(b1, W2);
    scatter_kernel<<<scat_blocks, 256>>>(ei, ew, out, 1);
    final_kernel<<<(N_NODES + 255) / 256, 256>>>(out, b2);
}

// round 16
// speedup vs baseline: 1.4820x; 1.4820x over previous
#include <cuda_runtime.h>
#include <cstdint>
#include <math.h>

#define N_NODES 100000
#define N_EDGES 3200000
#define D_FEAT  512
#define HID     16

// gemm1 tiling — measured-best R10 config
#define TPB_G     64
#define TILE_ROWS 256
#define RPT       4
#define XPITCH    36
#define GSMEM_FLOATS (D_FEAT * HID + TILE_ROWS * XPITCH)   // 8192 + 9216
#define GSMEM_BYTES  (GSMEM_FLOATS * 4)                    // 69632 B

// ---------------- scratch (device globals; no allocation allowed) ----------
__device__ float g_t1[N_NODES * HID];
__device__ float g_h1[N_NODES * HID];
__device__ float g_t2[N_NODES * HID];
__device__ int   g_is64;

// ---------------- helpers --------------------------------------------------
__device__ __forceinline__ unsigned long long ffma2(unsigned long long a,
                                                    unsigned long long b,
                                                    unsigned long long c) {
    unsigned long long d;
    asm("fma.rn.f32x2 %0, %1, %2, %3;" : "=l"(d) : "l"(a), "l"(b), "l"(c));
    return d;
}

// ---------------- edge_index dtype detection (parallel) --------------------
__global__ void detect_kernel(const void* eiv) {
    __shared__ int any32;
    if (threadIdx.x == 0) any32 = 0;
    __syncthreads();
    const int* p = (const int*)eiv;
    int local = 0;
    for (int i = threadIdx.x; i < 2048; i += 256)
        if (p[2 * i + 1] != 0) local = 1;
    if (local) atomicOr(&any32, 1);
    __syncthreads();
    if (threadIdx.x == 0) g_is64 = !any32;
}

// ---------------- zero accumulators ---------------------------------------
__global__ void zero_kernel(float* __restrict__ out) {
    int i = blockIdx.x * blockDim.x + threadIdx.x;
    const int total4 = N_NODES * HID / 4;
    if (i < total4) {
        float4 z = make_float4(0.f, 0.f, 0.f, 0.f);
        ((float4*)g_h1)[i] = z;
        ((float4*)out)[i]  = z;
    }
}

// ---------------- GEMM1: t1 = x @ W1  (R10 proven config) ------------------
__global__ void __launch_bounds__(TPB_G) gemm1_kernel(
        const float* __restrict__ x, const float* __restrict__ W1) {
    extern __shared__ float sm[];
    float* Ws = sm;                       // 8192 floats (full W1)
    float* xs = sm + D_FEAT * HID;        // 256 x 36 floats

    const int t = threadIdx.x;

    for (int i = t; i < D_FEAT * HID / 4; i += TPB_G)
        ((float4*)Ws)[i] = ((const float4*)W1)[i];

    const int row0 = blockIdx.x * TILE_ROWS;

    unsigned long long acc[RPT][8];
#pragma unroll
    for (int r = 0; r < RPT; r++)
#pragma unroll
        for (int j = 0; j < 8; j++) acc[r][j] = 0ULL;

    for (int kt = 0; kt < D_FEAT / 32; kt++) {
        const int k0 = kt * 32;
        __syncthreads();
#pragma unroll
        for (int i = 0; i < 32; i++) {
            int v   = i * TPB_G + t;
            int lr  = v >> 3;
            int sub = v & 7;
            int gr  = row0 + lr;
            if (gr >= N_NODES) gr = N_NODES - 1;
            float4 val = *(const float4*)(x + (size_t)gr * D_FEAT + k0 + sub * 4);
            *(float4*)(xs + lr * XPITCH + sub * 4) = val;
        }
        __syncthreads();

#pragma unroll
        for (int kk4 = 0; kk4 < 8; kk4++) {
            float4 xv[RPT];
#pragma unroll
            for (int r = 0; r < RPT; r++)
                xv[r] = *(const float4*)(xs + (t + TPB_G * r) * XPITCH + kk4 * 4);
#pragma unroll
            for (int kk = 0; kk < 4; kk++) {
                const ulonglong2* wrow =
                    (const ulonglong2*)(Ws + (k0 + kk4 * 4 + kk) * HID);
                ulonglong2 w0 = wrow[0], w1 = wrow[1];
                ulonglong2 w2 = wrow[2], w3 = wrow[3];
#pragma unroll
                for (int r = 0; r < RPT; r++) {
                    float xe = ((const float*)&xv[r])[kk];
                    unsigned long long xp;
                    unsigned int xb = __float_as_uint(xe);
                    asm("mov.b64 %0, {%1, %1};" : "=l"(xp) : "r"(xb));
                    acc[r][0] = ffma2(xp, w0.x, acc[r][0]);
                    acc[r][1] = ffma2(xp, w0.y, acc[r][1]);
                    acc[r][2] = ffma2(xp, w1.x, acc[r][2]);
                    acc[r][3] = ffma2(xp, w1.y, acc[r][3]);
                    acc[r][4] = ffma2(xp, w2.x, acc[r][4]);
                    acc[r][5] = ffma2(xp, w2.y, acc[r][5]);
                    acc[r][6] = ffma2(xp, w3.x, acc[r][6]);
                    acc[r][7] = ffma2(xp, w3.y, acc[r][7]);
                }
            }
        }
    }

#pragma unroll
    for (int r = 0; r < RPT; r++) {
        int gr = row0 + t + TPB_G * r;
        if (gr < N_NODES) {
            float o[16];
#pragma unroll
            for (int j = 0; j < 8; j++) {
                unsigned int lo, hi;
                asm("mov.b64 {%0, %1}, %2;" : "=r"(lo), "=r"(hi) : "l"(acc[r][j]));
                o[2 * j]     = __uint_as_float(lo);
                o[2 * j + 1] = __uint_as_float(hi);
            }
            float4* dst = (float4*)(g_t1 + (size_t)gr * HID);
            dst[0] = make_float4(o[0], o[1], o[2], o[3]);
            dst[1] = make_float4(o[4], o[5], o[6], o[7]);
            dst[2] = make_float4(o[8], o[9], o[10], o[11]);
            dst[3] = make_float4(o[12], o[13], o[14], o[15]);
        }
    }
}

// ---------------- edge scatter: acc[dst] += w * feat[src] ------------------
// One thread per (edge, 4-col chunk): proven best config.
__global__ void scatter_kernel(const void* __restrict__ eiv,
                               const float* __restrict__ ew,
                               float* __restrict__ out, int pass) {
    long long u = (long long)blockIdx.x * blockDim.x + threadIdx.x;
    const long long total = (long long)N_EDGES * 4;
    if (u >= total) return;
    int e = (int)(u >> 2);
    int c = (int)(u & 3);

    const float* feat = (pass == 0) ? g_t1 : g_t2;
    float*       acc  = (pass == 0) ? g_h1 : out;

    long long s, d;
    if (!g_is64) {
        const int* ei = (const int*)eiv;
        s = ei[e];
        d = ei[N_EDGES + e];
    } else {
        const long long* ei = (const long long*)eiv;
        s = ei[e];
        d = ei[N_EDGES + e];
    }
    float w = ew[e];
    float4 v = *(const float4*)(feat + s * HID + c * 4);
    float4 m = make_float4(w * v.x, w * v.y, w * v.z, w * v.w);
    atomicAdd((float4*)(acc + d * HID + c * 4), m);
}

// ---------------- mid: t2 = relu(h1 + b1) @ W2 -----------------------------
__global__ void mid_kernel(const float* __restrict__ b1,
                           const float* __restrict__ W2) {
    __shared__ float W2s[HID * HID];
    __shared__ float b1s[HID];
    int t = threadIdx.x;
    if (t < HID * HID) W2s[t] = W2[t];
    if (t < HID) b1s[t] = b1[t];
    __syncthreads();

    int node = blockIdx.x * blockDim.x + t;
    if (node >= N_NODES) return;

    float v[16];
    const float4* src = (const float4*)(g_h1 + (size_t)node * HID);
#pragma unroll
    for (int q = 0; q < 4; q++) {
        float4 f = src[q];
        v[4 * q] = f.x; v[4 * q + 1] = f.y; v[4 * q + 2] = f.z; v[4 * q + 3] = f.w;
    }
#pragma unroll
    for (int i = 0; i < 16; i++) v[i] = fmaxf(v[i] + b1s[i], 0.0f);

    float o[16];
#pragma unroll
    for (int j = 0; j < 16; j++) o[j] = 0.0f;
#pragma unroll
    for (int i = 0; i < 16; i++) {
        float vi = v[i];
#pragma unroll
        for (int j = 0; j < 16; j++) o[j] = fmaf(vi, W2s[i * 16 + j], o[j]);
    }

    float4* dst = (float4*)(g_t2 + (size_t)node * HID);
    dst[0] = make_float4(o[0], o[1], o[2], o[3]);
    dst[1] = make_float4(o[4], o[5], o[6], o[7]);
    dst[2] = make_float4(o[8], o[9], o[10], o[11]);
    dst[3] = make_float4(o[12], o[13], o[14], o[15]);
}

// ---------------- final: out = log_softmax(out + b2) -----------------------
__global__ void final_kernel(float* __restrict__ out,
                             const float* __restrict__ b2) {
    __shared__ float b2s[HID];
    if (threadIdx.x < HID) b2s[threadIdx.x] = b2[threadIdx.x];
    __syncthreads();

    int node = blockIdx.x * blockDim.x + threadIdx.x;
    if (node >= N_NODES) return;

    float o[16];
    float4* p = (float4*)(out + (size_t)node * HID);
#pragma unroll
    for (int q = 0; q < 4; q++) {
        float4 f = p[q];
        o[4 * q]     = f.x + b2s[4 * q];
        o[4 * q + 1] = f.y + b2s[4 * q + 1];
        o[4 * q + 2] = f.z + b2s[4 * q + 2];
        o[4 * q + 3] = f.w + b2s[4 * q + 3];
    }
    float m = o[0];
#pragma unroll
    for (int j = 1; j < 16; j++) m = fmaxf(m, o[j]);
    float ssum = 0.0f;
#pragma unroll
    for (int j = 0; j < 16; j++) ssum += expf(o[j] - m);
    float lse = m + logf(ssum);
#pragma unroll
    for (int j = 0; j < 16; j++) o[j] -= lse;

    p[0] = make_float4(o[0], o[1], o[2], o[3]);
    p[1] = make_float4(o[4], o[5], o[6], o[7]);
    p[2] = make_float4(o[8], o[9], o[10], o[11]);
    p[3] = make_float4(o[12], o[13], o[14], o[15]);
}

// ---------------- launch ---------------------------------------------------
extern "C" void kernel_launch(void* const* d_in, const int* in_sizes, int n_in,
                              void* d_out, int out_size) {
    const float* x  = (const float*)d_in[0];
    const void*  ei = d_in[1];
    const float* ew = (const float*)d_in[2];
    const float* W1 = (const float*)d_in[3];
    const float* b1 = (const float*)d_in[4];
    const float* W2 = (const float*)d_in[5];
    const float* b2 = (const float*)d_in[6];
    float* out = (float*)d_out;

    static int smem_set = 0;
    if (!smem_set) {
        cudaFuncSetAttribute(gemm1_kernel,
                             cudaFuncAttributeMaxDynamicSharedMemorySize,
                             GSMEM_BYTES);
        smem_set = 1;
    }

    detect_kernel<<<1, 256>>>(ei);
    zero_kernel<<<(N_NODES * HID / 4 + 255) / 256, 256>>>(out);
    gemm1_kernel<<<(N_NODES + TILE_ROWS - 1) / TILE_ROWS, TPB_G,
                   GSMEM_BYTES>>>(x, W1);

    const int scat_blocks = (int)(((long long)N_EDGES * 4 + 255) / 256);
    scatter_kernel<<<scat_blocks, 256>>>(ei, ew, out, 0);
    mid_kernel<<<(N_NODES + 255) / 256, 256>>>(b1, W2);
    scatter_kernel<<<scat_blocks, 256>>>(ei, ew, out, 1);
    final_kernel<<<(N_NODES + 255) / 256, 256>>>(out, b2);
}